// round 6
// baseline (speedup 1.0000x reference)
#include <cuda_runtime.h>

// qpNet: h = x @ W^T + b  (x: [B,5], W: [5,5], b: [5])
//        z = max(-h, -1000)   (closed-form separable QP, EPS=1e-3)
//
// Streaming, memory-bound. Each thread: 4 rows = 20 floats = 5 aligned float4
// loads + 5 float4 stores. W/b live in __constant__ memory (uniform-register
// path, zero thread-register cost) so occupancy is not register-limited.

#define NROWS_PER_THREAD 4
#define THREADS 256

__constant__ float cW[25];
__constant__ float cB[5];

__global__ __launch_bounds__(THREADS, 6)
void qpNet_kernel(const float4* __restrict__ x4,
                  float4*       __restrict__ out4,
                  int n_groups)
{
    int t = blockIdx.x * blockDim.x + threadIdx.x;
    if (t >= n_groups) return;

    int base = t * 5;

    // Front-batched streaming loads (evict-first; no reuse)
    float4 f0 = __ldcs(x4 + base + 0);
    float4 f1 = __ldcs(x4 + base + 1);
    float4 f2 = __ldcs(x4 + base + 2);
    float4 f3 = __ldcs(x4 + base + 3);
    float4 f4 = __ldcs(x4 + base + 4);

    float v[20] = {
        f0.x, f0.y, f0.z, f0.w,
        f1.x, f1.y, f1.z, f1.w,
        f2.x, f2.y, f2.z, f2.w,
        f3.x, f3.y, f3.z, f3.w,
        f4.x, f4.y, f4.z, f4.w
    };

    // Compute each row's 5 outputs into temps, then overwrite that row's
    // input slots — keeps live registers tight (in-place transform).
#pragma unroll
    for (int r = 0; r < NROWS_PER_THREAD; r++) {
        float t0, t1, t2, t3, t4;
        {
            float s0 = cB[0], s1 = cB[1], s2 = cB[2], s3 = cB[3], s4 = cB[4];
#pragma unroll
            for (int k = 0; k < 5; k++) {
                float xv = v[r * 5 + k];
                s0 = fmaf(xv, cW[0 * 5 + k], s0);
                s1 = fmaf(xv, cW[1 * 5 + k], s1);
                s2 = fmaf(xv, cW[2 * 5 + k], s2);
                s3 = fmaf(xv, cW[3 * 5 + k], s3);
                s4 = fmaf(xv, cW[4 * 5 + k], s4);
            }
            t0 = fmaxf(-s0, -1000.0f);
            t1 = fmaxf(-s1, -1000.0f);
            t2 = fmaxf(-s2, -1000.0f);
            t3 = fmaxf(-s3, -1000.0f);
            t4 = fmaxf(-s4, -1000.0f);
        }
        v[r * 5 + 0] = t0;
        v[r * 5 + 1] = t1;
        v[r * 5 + 2] = t2;
        v[r * 5 + 3] = t3;
        v[r * 5 + 4] = t4;
    }

    __stcs(out4 + base + 0, make_float4(v[0],  v[1],  v[2],  v[3]));
    __stcs(out4 + base + 1, make_float4(v[4],  v[5],  v[6],  v[7]));
    __stcs(out4 + base + 2, make_float4(v[8],  v[9],  v[10], v[11]));
    __stcs(out4 + base + 3, make_float4(v[12], v[13], v[14], v[15]));
    __stcs(out4 + base + 4, make_float4(v[16], v[17], v[18], v[19]));
}

extern "C" void kernel_launch(void* const* d_in, const int* in_sizes, int n_in,
                              void* d_out, int out_size)
{
    const float* x    = (const float*)d_in[0];   // [B, 5]
    const float* W    = (const float*)d_in[1];   // [5, 5]
    const float* b_fc = (const float*)d_in[2];   // [5]
    float* out = (float*)d_out;                  // [B, 5]

    // Stage weights/bias into __constant__ memory (D2D memcpy-to-symbol:
    // graph-capturable, becomes a memcpy node ordered before the kernel).
    cudaMemcpyToSymbolAsync(cW, W,    25 * sizeof(float), 0,
                            cudaMemcpyDeviceToDevice, 0);
    cudaMemcpyToSymbolAsync(cB, b_fc,  5 * sizeof(float), 0,
                            cudaMemcpyDeviceToDevice, 0);

    int n_elems  = in_sizes[0];                  // B * 5
    int n_rows   = n_elems / 5;                  // B
    int n_groups = n_rows / NROWS_PER_THREAD;    // B/4 (B = 4194304, divisible)

    int blocks = (n_groups + THREADS - 1) / THREADS;
    qpNet_kernel<<<blocks, THREADS>>>(
        (const float4*)x, (float4*)out, n_groups);
}

// round 9
// speedup vs baseline: 1.1231x; 1.1231x over previous
#include <cuda_runtime.h>

// qpNet: h = x @ W^T + b  (x: [B,5], W: [5,5], b: [5]);  z = max(-h, -1000)
//
// Coalesced streaming via smem staging:
//  - global loads/stores are block-coalesced float4 (ideal 4 wavefronts/warp-inst)
//  - per-thread row access happens in shared memory (LDS.128 @ 80B stride is
//    bank-conflict-free: banks (tid*20+i*4)%32 distinct within each 8-lane phase)

#define THREADS 256
#define F4_PER_BLOCK (THREADS * 5)   // 1280 float4 = 20 KB: 256 threads x 4 rows x 5 floats

__global__ __launch_bounds__(THREADS)
void qpNet_kernel(const float4* __restrict__ x4,
                  const float*  __restrict__ W,
                  const float*  __restrict__ b,
                  float4*       __restrict__ out4)
{
    __shared__ float4 s[F4_PER_BLOCK];
    __shared__ float  sw[25];
    __shared__ float  sb[5];

    int tid = threadIdx.x;
    long long blk = (long long)blockIdx.x * F4_PER_BLOCK;

    if (tid < 25) sw[tid] = W[tid];
    if (tid < 5)  sb[tid] = b[tid];

    // Phase 1: block-coalesced loads -> smem (STS.128, conflict-free)
#pragma unroll
    for (int i = 0; i < 5; i++) {
        s[i * THREADS + tid] = __ldcs(x4 + blk + i * THREADS + tid);
    }
    __syncthreads();

    // Phase 2: each thread owns 4 contiguous rows = smem float4 [tid*5 .. tid*5+4]
    float v[20];
#pragma unroll
    for (int i = 0; i < 5; i++) {
        float4 f = s[tid * 5 + i];
        v[i * 4 + 0] = f.x;
        v[i * 4 + 1] = f.y;
        v[i * 4 + 2] = f.z;
        v[i * 4 + 3] = f.w;
    }

    float w[25];
#pragma unroll
    for (int i = 0; i < 25; i++) w[i] = sw[i];
    float bb[5];
#pragma unroll
    for (int j = 0; j < 5; j++) bb[j] = sb[j];

#pragma unroll
    for (int r = 0; r < 4; r++) {
        float s0 = bb[0], s1 = bb[1], s2 = bb[2], s3 = bb[3], s4 = bb[4];
#pragma unroll
        for (int k = 0; k < 5; k++) {
            float xv = v[r * 5 + k];
            s0 = fmaf(xv, w[0 * 5 + k], s0);
            s1 = fmaf(xv, w[1 * 5 + k], s1);
            s2 = fmaf(xv, w[2 * 5 + k], s2);
            s3 = fmaf(xv, w[3 * 5 + k], s3);
            s4 = fmaf(xv, w[4 * 5 + k], s4);
        }
        v[r * 5 + 0] = fmaxf(-s0, -1000.0f);
        v[r * 5 + 1] = fmaxf(-s1, -1000.0f);
        v[r * 5 + 2] = fmaxf(-s2, -1000.0f);
        v[r * 5 + 3] = fmaxf(-s3, -1000.0f);
        v[r * 5 + 4] = fmaxf(-s4, -1000.0f);
    }

    // Write results back to the SAME smem slots this thread read (same-thread
    // RAW only -> no extra sync needed before these stores).
#pragma unroll
    for (int i = 0; i < 5; i++) {
        s[tid * 5 + i] = make_float4(v[i * 4 + 0], v[i * 4 + 1],
                                     v[i * 4 + 2], v[i * 4 + 3]);
    }
    __syncthreads();

    // Phase 3: block-coalesced stores
#pragma unroll
    for (int i = 0; i < 5; i++) {
        __stcs(out4 + blk + i * THREADS + tid, s[i * THREADS + tid]);
    }
}

extern "C" void kernel_launch(void* const* d_in, const int* in_sizes, int n_in,
                              void* d_out, int out_size)
{
    const float* x    = (const float*)d_in[0];   // [B, 5]
    const float* W    = (const float*)d_in[1];   // [5, 5]
    const float* b_fc = (const float*)d_in[2];   // [5]
    float* out = (float*)d_out;                  // [B, 5]

    int n_elems = in_sizes[0];                   // B * 5 = 20,971,520
    int n_f4    = n_elems / 4;                   // total float4
    int blocks  = n_f4 / F4_PER_BLOCK;           // 4096 (B=4194304 divides exactly)

    qpNet_kernel<<<blocks, THREADS>>>(
        (const float4*)x, W, b_fc, (float4*)out);
}

// round 13
// speedup vs baseline: 1.2041x; 1.0722x over previous
#include <cuda_runtime.h>
#include <cstdint>

// qpNet: h = x @ W^T + b  (x: [B,5], W: [5,5], b: [5]);  z = max(-h, -1000)
//
// Persistent pipelined streaming kernel:
//   - TMA 1D bulk loads (cp.async.bulk, mbarrier complete_tx) fill a 2-stage
//     20KB smem ring; loads for future tiles overlap compute of current tile.
//   - Compute: per-thread 4 rows via LDS.128 (80B stride, bank-conflict-free),
//     results written back in place via STS.128.
//   - TMA bulk stores (bulk_group) drain results asynchronously.
// Warps never touch global memory directly -> load concurrency is decoupled
// from warp count / phase structure; DRAM BW becomes the only limiter.

#define THREADS        256
#define F4_PER_TILE    (THREADS * 5)        // 1280 float4 = 20KB (1024 rows)
#define TILE_BYTES     (F4_PER_TILE * 16)   // 20480
#define TILES_PER_CTA  4
#define STAGES         2

__device__ __forceinline__ uint32_t smem_u32(const void* p) {
    return (uint32_t)__cvta_generic_to_shared(p);
}

__device__ __forceinline__ void mbar_init(uint32_t mbar, uint32_t count) {
    asm volatile("mbarrier.init.shared.b64 [%0], %1;"
                 :: "r"(mbar), "r"(count) : "memory");
}

__device__ __forceinline__ void mbar_expect_tx(uint32_t mbar, uint32_t bytes) {
    asm volatile("mbarrier.arrive.expect_tx.shared.b64 _, [%0], %1;"
                 :: "r"(mbar), "r"(bytes) : "memory");
}

__device__ __forceinline__ void mbar_wait(uint32_t mbar, uint32_t parity) {
    uint32_t done;
    asm volatile(
        "{\n\t"
        ".reg .pred p;\n\t"
        "mbarrier.try_wait.parity.acquire.cta.shared::cta.b64 p, [%1], %2;\n\t"
        "selp.b32 %0, 1, 0, p;\n\t"
        "}"
        : "=r"(done) : "r"(mbar), "r"(parity) : "memory");
    if (!done) {
        asm volatile(
            "{\n\t"
            ".reg .pred P1;\n\t"
            "WAIT_LOOP_%=:\n\t"
            "mbarrier.try_wait.parity.acquire.cta.shared::cta.b64 P1, [%0], %1, 0x989680;\n\t"
            "@P1 bra.uni WAIT_DONE_%=;\n\t"
            "bra.uni WAIT_LOOP_%=;\n\t"
            "WAIT_DONE_%=:\n\t"
            "}"
            :: "r"(mbar), "r"(parity) : "memory");
    }
}

__device__ __forceinline__ void bulk_load(uint32_t dst_smem, const void* src_gmem,
                                          uint32_t bytes, uint32_t mbar) {
    asm volatile(
        "cp.async.bulk.shared::cta.global.mbarrier::complete_tx::bytes "
        "[%0], [%1], %2, [%3];"
        :: "r"(dst_smem), "l"(src_gmem), "r"(bytes), "r"(mbar) : "memory");
}

__device__ __forceinline__ void bulk_store(void* dst_gmem, uint32_t src_smem,
                                           uint32_t bytes) {
    asm volatile(
        "cp.async.bulk.global.shared::cta.bulk_group [%0], [%1], %2;"
        :: "l"(dst_gmem), "r"(src_smem), "r"(bytes) : "memory");
}

__device__ __forceinline__ void bulk_commit() {
    asm volatile("cp.async.bulk.commit_group;" ::: "memory");
}

template <int N>
__device__ __forceinline__ void bulk_wait() {
    asm volatile("cp.async.bulk.wait_group %0;" :: "n"(N) : "memory");
}

__device__ __forceinline__ void fence_async_proxy() {
    asm volatile("fence.proxy.async.shared::cta;" ::: "memory");
}

__global__ __launch_bounds__(THREADS)
void qpNet_kernel(const float* __restrict__ x,
                  const float* __restrict__ W,
                  const float* __restrict__ b,
                  float* __restrict__ out)
{
    __shared__ __align__(16) float4 buf[STAGES][F4_PER_TILE];
    __shared__ __align__(8) unsigned long long mbar_storage[STAGES];

    const int tid = threadIdx.x;
    uint32_t mb[STAGES];
#pragma unroll
    for (int s = 0; s < STAGES; s++) mb[s] = smem_u32(&mbar_storage[s]);

    if (tid == 0) {
#pragma unroll
        for (int s = 0; s < STAGES; s++) mbar_init(mb[s], 1);
    }
    __syncthreads();

    // Weights/bias (warp-uniform, L1-resident after first wave)
    float w[25];
#pragma unroll
    for (int i = 0; i < 25; i++) w[i] = __ldg(W + i);
    float bb[5];
#pragma unroll
    for (int j = 0; j < 5; j++) bb[j] = __ldg(b + j);

    // Grid-stride tile schedule: tile_id(j) = blockIdx.x + j*gridDim.x
    const char* xb  = (const char*)x;
    char*       ob  = (char*)out;

    // Prologue: fill the ring
    if (tid == 0) {
#pragma unroll
        for (int j = 0; j < STAGES; j++) {
            long long off = ((long long)blockIdx.x + (long long)j * gridDim.x)
                            * (long long)TILE_BYTES;
            mbar_expect_tx(mb[j], TILE_BYTES);
            bulk_load(smem_u32(&buf[j][0]), xb + off, TILE_BYTES, mb[j]);
        }
    }

#pragma unroll
    for (int j = 0; j < TILES_PER_CTA; j++) {
        const int s = j & 1;
        const uint32_t parity = (j >> 1) & 1;
        long long off = ((long long)blockIdx.x + (long long)j * gridDim.x)
                        * (long long)TILE_BYTES;

        // Wait for this tile's TMA load
        mbar_wait(mb[s], parity);

        // Compute: thread owns 4 rows = smem float4 [tid*5 .. tid*5+4]
        // (80B stride -> bank-conflict-free LDS.128/STS.128)
        float v[20];
#pragma unroll
        for (int i = 0; i < 5; i++) {
            float4 f = buf[s][tid * 5 + i];
            v[i * 4 + 0] = f.x; v[i * 4 + 1] = f.y;
            v[i * 4 + 2] = f.z; v[i * 4 + 3] = f.w;
        }

#pragma unroll
        for (int r = 0; r < 4; r++) {
            float s0 = bb[0], s1 = bb[1], s2 = bb[2], s3 = bb[3], s4 = bb[4];
#pragma unroll
            for (int k = 0; k < 5; k++) {
                float xv = v[r * 5 + k];
                s0 = fmaf(xv, w[0 * 5 + k], s0);
                s1 = fmaf(xv, w[1 * 5 + k], s1);
                s2 = fmaf(xv, w[2 * 5 + k], s2);
                s3 = fmaf(xv, w[3 * 5 + k], s3);
                s4 = fmaf(xv, w[4 * 5 + k], s4);
            }
            v[r * 5 + 0] = fmaxf(-s0, -1000.0f);
            v[r * 5 + 1] = fmaxf(-s1, -1000.0f);
            v[r * 5 + 2] = fmaxf(-s2, -1000.0f);
            v[r * 5 + 3] = fmaxf(-s3, -1000.0f);
            v[r * 5 + 4] = fmaxf(-s4, -1000.0f);
        }

        // Write results back in place (same-thread slots, no extra sync)
#pragma unroll
        for (int i = 0; i < 5; i++) {
            buf[s][tid * 5 + i] = make_float4(v[i * 4 + 0], v[i * 4 + 1],
                                              v[i * 4 + 2], v[i * 4 + 3]);
        }
        __syncthreads();   // all STS visible before async-proxy store

        if (tid == 0) {
            fence_async_proxy();
            bulk_store(ob + off, smem_u32(&buf[s][0]), TILE_BYTES);
            bulk_commit();

            int jn = j + STAGES;
            if (jn < TILES_PER_CTA) {
                // Stage s is reused by tile jn: its store (tile j, just
                // committed) must fully drain first.
                bulk_wait<0>();
                long long offn = ((long long)blockIdx.x
                                  + (long long)jn * gridDim.x)
                                 * (long long)TILE_BYTES;
                mbar_expect_tx(mb[s], TILE_BYTES);
                bulk_load(smem_u32(&buf[s][0]), xb + offn, TILE_BYTES, mb[s]);
            }
        }
        // No barrier here: consumers of tile j+1 gate on mbar_wait; the
        // expect_tx re-arm above happens after __syncthreads() of tile j,
        // so every thread has already passed the previous wait on mb[s].
    }

    // Drain pending bulk stores before exit (gmem visibility insurance)
    if (tid == 0) bulk_wait<0>();
}

extern "C" void kernel_launch(void* const* d_in, const int* in_sizes, int n_in,
                              void* d_out, int out_size)
{
    const float* x    = (const float*)d_in[0];   // [B, 5]
    const float* W    = (const float*)d_in[1];   // [5, 5]
    const float* b_fc = (const float*)d_in[2];   // [5]
    float* out = (float*)d_out;                  // [B, 5]

    int n_elems = in_sizes[0];                   // B*5 = 20,971,520 floats
    int n_f4    = n_elems / 4;                   // 5,242,880 float4
    int n_tiles = n_f4 / F4_PER_TILE;            // 4096
    int blocks  = n_tiles / TILES_PER_CTA;       // 1024

    qpNet_kernel<<<blocks, THREADS>>>(x, W, b_fc, out);
}